// round 1
// baseline (speedup 1.0000x reference)
#include <cuda_runtime.h>

// Problem constants
#define NB   16
#define CC   64
#define WHT  16384
#define CWH  (CC * WHT)

// Scratch (device globals; no allocation allowed)
__device__ float g_gram[2 * NB * CC * CC];     // [mat][n][c][d]
__device__ float g_sums[2 * NB * CC];          // [mat][n][c]
__device__ float g_logits[NB * 2 * CC * CC];   // [n][k(2C)][d]
__device__ float g_att[NB * 2 * CC * CC];      // [n][k(2C)][d]

typedef unsigned long long u64;

__device__ __forceinline__ u64 splat2(float x) {
    u64 r; unsigned xi = __float_as_uint(x);
    asm("mov.b64 %0, {%1, %1};" : "=l"(r) : "r"(xi));
    return r;
}
__device__ __forceinline__ void ffma2(u64 &acc, u64 a, u64 b) {
    asm("fma.rn.f32x2 %0, %1, %2, %3;" : "=l"(acc) : "l"(a), "l"(b), "l"(acc));
}
__device__ __forceinline__ float2 unpk(u64 v) {
    unsigned lo, hi;
    asm("mov.b64 {%0, %1}, %2;" : "=r"(lo), "=r"(hi) : "l"(v));
    return make_float2(__uint_as_float(lo), __uint_as_float(hi));
}

// ---------------------------------------------------------------------------
// Kernel 0: zero the accumulated scratch (graph replays reuse globals)
// ---------------------------------------------------------------------------
__global__ void zero_kernel() {
    int i = blockIdx.x * blockDim.x + threadIdx.x;
    if (i < 2 * NB * CC * CC) g_gram[i] = 0.0f;
    if (i < 2 * NB * CC)      g_sums[i] = 0.0f;
}

// ---------------------------------------------------------------------------
// Kernel 1: split-K gram  G[n] = x[n] x[n]^T  (64x64) and row-sums s[n]
// grid = 2 mats * 16 n * 64 splits = 2048 blocks, 256 threads
// Each block handles 256 pixels in 8 tiles of 32.
// ---------------------------------------------------------------------------
__global__ void __launch_bounds__(256) gram_kernel(const float* __restrict__ xR,
                                                   const float* __restrict__ xT) {
    int b = blockIdx.x;
    int split = b & 63; b >>= 6;
    int n = b & 15;
    int mat = b >> 4;
    const float* src = (mat ? xT : xR) + n * CWH;
    int p0 = split * 256;

    __shared__ float sm[32][66];   // [pixel][channel], pad 66 for bank spread

    int tid = threadIdx.x;
    int p_l = tid & 31;            // pixel lane for loading
    int c0  = tid >> 5;            // = warp id (0..7)
    int ri  = tid >> 4;            // 0..15 -> rows 4*ri..4*ri+3
    int cj  = tid & 15;            // cols {2cj,2cj+1, 2cj+32,2cj+33}

    u64 acc[4][2];
#pragma unroll
    for (int i = 0; i < 4; i++) { acc[i][0] = 0ull; acc[i][1] = 0ull; }
    float csum[8];
#pragma unroll
    for (int i = 0; i < 8; i++) csum[i] = 0.0f;

    for (int t = 0; t < 8; t++) {
        int pp = p0 + t * 32 + p_l;
#pragma unroll
        for (int i = 0; i < 8; i++) {
            int c = c0 + 8 * i;
            float v = src[c * WHT + pp];   // coalesced 128B per warp
            sm[p_l][c] = v;
            csum[i] += v;
        }
        __syncthreads();
#pragma unroll
        for (int p = 0; p < 32; p++) {
            float2 alo = *(const float2*)&sm[p][4 * ri];
            float2 ahi = *(const float2*)&sm[p][4 * ri + 2];
            u64 b0 = *(const u64*)&sm[p][2 * cj];
            u64 b1 = *(const u64*)&sm[p][2 * cj + 32];
            u64 A0 = splat2(alo.x), A1 = splat2(alo.y);
            u64 A2 = splat2(ahi.x), A3 = splat2(ahi.y);
            ffma2(acc[0][0], A0, b0); ffma2(acc[0][1], A0, b1);
            ffma2(acc[1][0], A1, b0); ffma2(acc[1][1], A1, b1);
            ffma2(acc[2][0], A2, b0); ffma2(acc[2][1], A2, b1);
            ffma2(acc[3][0], A3, b0); ffma2(acc[3][1], A3, b1);
        }
        __syncthreads();
    }

    float* gbase = g_gram + (mat * NB + n) * CC * CC;
#pragma unroll
    for (int i = 0; i < 4; i++) {
        int row = 4 * ri + i;
#pragma unroll
        for (int jj = 0; jj < 2; jj++) {
            float2 v = unpk(acc[i][jj]);
            int col = 2 * cj + 32 * jj;
            atomicAdd(&gbase[row * CC + col], v.x);
            atomicAdd(&gbase[row * CC + col + 1], v.y);
        }
    }

    // channel sums: each warp owns channels {c0 + 8i}, reduce over 32 pixel lanes
    float* sbase = g_sums + (mat * NB + n) * CC;
#pragma unroll
    for (int i = 0; i < 8; i++) {
        float v = csum[i];
#pragma unroll
        for (int o = 16; o > 0; o >>= 1) v += __shfl_down_sync(0xffffffffu, v, o);
        if (p_l == 0) atomicAdd(&sbase[c0 + 8 * i], v);
    }
}

// ---------------------------------------------------------------------------
// Kernel 2a: logits  S = W G W^T + b u^T + u b^T + WH b b^T   (per n, per mat)
// grid = 32 (mat*16 + n), 256 threads
// ---------------------------------------------------------------------------
__global__ void __launch_bounds__(256) logits_kernel(const float* __restrict__ WR,
                                                     const float* __restrict__ bR,
                                                     const float* __restrict__ WT,
                                                     const float* __restrict__ bT) {
    int n = blockIdx.x & 15;
    int mat = blockIdx.x >> 4;
    const float* W  = mat ? WT : WR;
    const float* bv = mat ? bT : bR;

    __shared__ float sW[64][64];
    __shared__ float sGM[64][65];   // holds G, then reused for M = W*G
    __shared__ float sb[64], ssum[64], su[64];

    int tid = threadIdx.x;
    const float* gsrc = g_gram + (mat * NB + n) * CC * CC;
    for (int i = tid; i < 4096; i += 256) {
        sW[i >> 6][i & 63]  = W[i];
        sGM[i >> 6][i & 63] = gsrc[i];
    }
    if (tid < 64) {
        sb[tid]   = bv[tid];
        ssum[tid] = g_sums[(mat * NB + n) * CC + tid];
    }
    __syncthreads();

    if (tid < 64) {
        float u = 0.0f;
        for (int f = 0; f < 64; f++) u += sW[tid][f] * ssum[f];
        su[tid] = u;
    }

    int r = tid >> 4, q = tid & 15;
    // M = W * G  (into registers)
    float acc[4][4];
#pragma unroll
    for (int i = 0; i < 4; i++)
#pragma unroll
        for (int j = 0; j < 4; j++) acc[i][j] = 0.0f;
    for (int f = 0; f < 64; f++) {
        float wv[4], gv[4];
#pragma unroll
        for (int i = 0; i < 4; i++) wv[i] = sW[4 * r + i][f];
#pragma unroll
        for (int j = 0; j < 4; j++) gv[j] = sGM[f][4 * q + j];
#pragma unroll
        for (int i = 0; i < 4; i++)
#pragma unroll
            for (int j = 0; j < 4; j++) acc[i][j] = fmaf(wv[i], gv[j], acc[i][j]);
    }
    __syncthreads();   // all reads of G done
#pragma unroll
    for (int i = 0; i < 4; i++)
#pragma unroll
        for (int j = 0; j < 4; j++) sGM[4 * r + i][4 * q + j] = acc[i][j];
    __syncthreads();

    // S = M * W^T
#pragma unroll
    for (int i = 0; i < 4; i++)
#pragma unroll
        for (int j = 0; j < 4; j++) acc[i][j] = 0.0f;
    for (int e = 0; e < 64; e++) {
        float mv[4], wv[4];
#pragma unroll
        for (int i = 0; i < 4; i++) mv[i] = sGM[4 * r + i][e];
#pragma unroll
        for (int j = 0; j < 4; j++) wv[j] = sW[4 * q + j][e];
#pragma unroll
        for (int i = 0; i < 4; i++)
#pragma unroll
            for (int j = 0; j < 4; j++) acc[i][j] = fmaf(mv[i], wv[j], acc[i][j]);
    }

    float* lbase = g_logits + n * (2 * CC * CC);
#pragma unroll
    for (int i = 0; i < 4; i++) {
        int ci = 4 * r + i;
#pragma unroll
        for (int j = 0; j < 4; j++) {
            int dj = 4 * q + j;
            float L = acc[i][j] + sb[ci] * su[dj] + su[ci] * sb[dj]
                    + 16384.0f * sb[ci] * sb[dj];
            lbase[(mat * CC + ci) * CC + dj] = L;
        }
    }
}

// ---------------------------------------------------------------------------
// Kernel 2b: softmax over the 128 rows, per (n, column)
// grid = 16, 64 threads (one per column)
// ---------------------------------------------------------------------------
__global__ void __launch_bounds__(64) softmax_kernel() {
    int n = blockIdx.x;
    int col = threadIdx.x;
    const float* L = g_logits + n * (2 * CC * CC) + col;
    float m = -3.0e38f;
    for (int k = 0; k < 128; k++) m = fmaxf(m, L[k * 64]);
    float s = 0.0f;
    for (int k = 0; k < 128; k++) s += expf(L[k * 64] - m);
    float inv = 1.0f / s;
    float* A = g_att + n * (2 * CC * CC) + col;
    for (int k = 0; k < 128; k++) A[k * 64] = expf(L[k * 64] - m) * inv;
}

// ---------------------------------------------------------------------------
// Kernel 3: out[n,c,p] = sum_k xcat[n,k,p] * att[n,k,c]
// GEMM per batch: [64 x 128] att^T applied to [128 x WH]
// grid = (WH/128, 16), 256 threads. Block output tile: 64c x 128p.
// ---------------------------------------------------------------------------
__global__ void __launch_bounds__(256) out_kernel(const float* __restrict__ xR,
                                                  const float* __restrict__ xT,
                                                  float* __restrict__ out) {
    int n  = blockIdx.y;
    int p0 = blockIdx.x * 128;

    __shared__ float att_s[128][68];   // [k][c], pad 68 keeps float4 alignment
    __shared__ float xs[16][132];      // [k_local][p], pad 132

    int tid = threadIdx.x;
    const float* attp = g_att + n * (2 * CC * CC);
#pragma unroll
    for (int i = 0; i < 32; i++) {
        int idx = tid + i * 256;
        att_s[idx >> 6][idx & 63] = attp[idx];
    }

    int ci = tid >> 4;   // rows 4*ci..4*ci+3
    int pj = tid & 15;   // pixels {2pj,2pj+1} + 32s, s=0..3

    u64 acc[4][4];
#pragma unroll
    for (int i = 0; i < 4; i++)
#pragma unroll
        for (int s = 0; s < 4; s++) acc[i][s] = 0ull;

    const float* baseR = xR + n * CWH + p0;
    const float* baseT = xT + n * CWH + p0;
    __syncthreads();

    for (int kt = 0; kt < 8; kt++) {
        const float* src = (kt < 4) ? baseR : baseT;
        int kbase = (kt < 4) ? kt * 16 : (kt - 4) * 16;
#pragma unroll
        for (int i = 0; i < 8; i++) {
            int idx = tid + i * 256;
            int kl = idx >> 7, p = idx & 127;
            xs[kl][p] = src[(kbase + kl) * WHT + p];
        }
        __syncthreads();
#pragma unroll
        for (int k = 0; k < 16; k++) {
            float4 a = *(const float4*)&att_s[kt * 16 + k][4 * ci];
            u64 A0 = splat2(a.x), A1 = splat2(a.y), A2 = splat2(a.z), A3 = splat2(a.w);
            u64 B0 = *(const u64*)&xs[k][2 * pj];
            u64 B1 = *(const u64*)&xs[k][2 * pj + 32];
            u64 B2 = *(const u64*)&xs[k][2 * pj + 64];
            u64 B3 = *(const u64*)&xs[k][2 * pj + 96];
            ffma2(acc[0][0], A0, B0); ffma2(acc[0][1], A0, B1);
            ffma2(acc[0][2], A0, B2); ffma2(acc[0][3], A0, B3);
            ffma2(acc[1][0], A1, B0); ffma2(acc[1][1], A1, B1);
            ffma2(acc[1][2], A1, B2); ffma2(acc[1][3], A1, B3);
            ffma2(acc[2][0], A2, B0); ffma2(acc[2][1], A2, B1);
            ffma2(acc[2][2], A2, B2); ffma2(acc[2][3], A2, B3);
            ffma2(acc[3][0], A3, B0); ffma2(acc[3][1], A3, B1);
            ffma2(acc[3][2], A3, B2); ffma2(acc[3][3], A3, B3);
        }
        __syncthreads();
    }

    float* ob = out + n * CWH + p0;
#pragma unroll
    for (int i = 0; i < 4; i++) {
        int c = 4 * ci + i;
#pragma unroll
        for (int s = 0; s < 4; s++) {
            float2 v = unpk(acc[i][s]);
            int p = 2 * pj + 32 * s;
            *(float2*)&ob[c * WHT + p] = v;
        }
    }
}

// ---------------------------------------------------------------------------
extern "C" void kernel_launch(void* const* d_in, const int* in_sizes, int n_in,
                              void* d_out, int out_size) {
    const float* xR = (const float*)d_in[0];
    const float* xT = (const float*)d_in[1];
    const float* WR = (const float*)d_in[2];
    const float* bR = (const float*)d_in[3];
    const float* WT = (const float*)d_in[4];
    const float* bT = (const float*)d_in[5];
    float* out = (float*)d_out;

    zero_kernel<<<(2 * NB * CC * CC + 255) / 256, 256>>>();
    gram_kernel<<<2 * NB * 64, 256>>>(xR, xT);
    logits_kernel<<<2 * NB, 256>>>(WR, bR, WT, bT);
    softmax_kernel<<<NB, 64>>>();
    out_kernel<<<dim3(WHT / 128, NB), 256>>>(xR, xT, out);
}